// round 1
// baseline (speedup 1.0000x reference)
#include <cuda_runtime.h>
#include <cuda_fp16.h>

// LBP forward: out[n,f,h,w] = sum_p 2^p * sigmoid((samp - cen)/0.1)
// sigmoid(y) = 0.5 + 0.5*tanh(y/2)  ->  bits = 0.5 + 0.5*tanh(5*diff)
// out = 7.5 + 0.5 * sum_p 2^p * tanh(5*diff_p)
//
// Shapes: input (32,64,56,56) f32, kernels (128,4,2) i32 in [0,3),
//         projection_map (128,4) i32 in [0,64). out (32,128,56,56) f32.

#define N_ 32
#define D_ 64
#define H_ 56
#define W_ 56
#define F_ 128
#define P_ 4
#define HW_ (H_ * W_)
#define WQ_ (W_ / 4)           // 14 quads per row
#define TOTAL_QUADS (N_ * F_ * H_ * WQ_)   // 3,211,264

__device__ __forceinline__ float2 tanh2_approx(float a, float b) {
    __half2 h = __floats2half2_rn(a, b);
    unsigned hin = *reinterpret_cast<unsigned*>(&h);
    unsigned hout;
    asm("tanh.approx.f16x2 %0, %1;" : "=r"(hout) : "r"(hin));
    __half2 r = *reinterpret_cast<__half2*>(&hout);
    return __half22float2(r);
}

__global__ __launch_bounds__(256) void lbp_quad_kernel(
    const float* __restrict__ in,
    const int*   __restrict__ kern,   // (F,P,2)
    const int*   __restrict__ pm,     // (F,P)
    float*       __restrict__ out)
{
    int idx = blockIdx.x * blockDim.x + threadIdx.x;
    if (idx >= TOTAL_QUADS) return;

    int wq = idx % WQ_;
    int w  = wq * 4;
    int t  = idx / WQ_;
    int h  = t % H_;
    t /= H_;
    int f  = t % F_;
    int n  = t / F_;

    const float* __restrict__ inn = in + (size_t)n * D_ * HW_;

    float acc0 = 7.5f, acc1 = 7.5f, acc2 = 7.5f, acc3 = 7.5f;

#pragma unroll
    for (int p = 0; p < P_; p++) {
        int c  = __ldg(&pm[f * P_ + p]);
        int dy = __ldg(&kern[(f * P_ + p) * 2 + 0]) - 1;
        int dx = __ldg(&kern[(f * P_ + p) * 2 + 1]) - 1;

        const float* __restrict__ plane = inn + c * HW_;

        // center values (always in range, 16B aligned)
        float4 cen = *reinterpret_cast<const float4*>(plane + h * W_ + w);

        // sampled values at (h+dy, w+dx .. w+3+dx), zero outside
        float s0 = 0.f, s1 = 0.f, s2 = 0.f, s3 = 0.f;
        int hh = h + dy;
        if (hh >= 0 && hh < H_) {
            const float* __restrict__ row = plane + hh * W_;
            float4 m = *reinterpret_cast<const float4*>(row + w);
            if (dx == 0) {
                s0 = m.x; s1 = m.y; s2 = m.z; s3 = m.w;
            } else if (dx < 0) {
                float left = (w > 0) ? __ldg(row + w - 1) : 0.f;
                s0 = left; s1 = m.x; s2 = m.y; s3 = m.z;
            } else {
                float right = (w + 4 < W_) ? __ldg(row + w + 4) : 0.f;
                s0 = m.y; s1 = m.z; s2 = m.w; s3 = right;
            }
        }

        float wp = 0.5f * (float)(1 << p);   // 2^p * 0.5
        float2 t01 = tanh2_approx((s0 - cen.x) * 5.f, (s1 - cen.y) * 5.f);
        float2 t23 = tanh2_approx((s2 - cen.z) * 5.f, (s3 - cen.w) * 5.f);
        acc0 = fmaf(wp, t01.x, acc0);
        acc1 = fmaf(wp, t01.y, acc1);
        acc2 = fmaf(wp, t23.x, acc2);
        acc3 = fmaf(wp, t23.y, acc3);
    }

    float4 o = make_float4(acc0, acc1, acc2, acc3);
    *reinterpret_cast<float4*>(out + ((size_t)(n * F_ + f) * HW_ + h * W_ + w)) = o;
}

extern "C" void kernel_launch(void* const* d_in, const int* in_sizes, int n_in,
                              void* d_out, int out_size)
{
    const float* in   = (const float*)d_in[0];
    const int*   kern = (const int*)d_in[1];
    const int*   pm   = (const int*)d_in[2];
    float*       out  = (float*)d_out;

    int threads = 256;
    int blocks  = (TOTAL_QUADS + threads - 1) / threads;   // 12544
    lbp_quad_kernel<<<blocks, threads>>>(in, kern, pm, out);
}